// round 1
// baseline (speedup 1.0000x reference)
#include <cuda_runtime.h>
#include <cuda_bf16.h>

// OccupancyGridForestAS: 4.19M points, 8x8x8 block lookup -> 64 trees of 64^3 voxels.
//
// inputs (metadata order):
//   d_in[0]: pts            float32 [N_PTS, 3]          (12,582,912 elems)
//   d_in[1]: occ_val_grid   float32 [64, 64, 64, 64]    (16,777,216 elems)
//   d_in[2]: block_lookup   int32   [8, 8, 8]           (512 elems)
// output: float32 [N_PTS]

#define RES   64
#define LDIM  8

__global__ void __launch_bounds__(256)
occ_forest_kernel(const float4* __restrict__ pts4,
                  const float*  __restrict__ occ,
                  const int*    __restrict__ lut,
                  float*        __restrict__ out4,
                  int n4)
{
    int t = blockIdx.x * blockDim.x + threadIdx.x;
    if (t >= n4) return;

    // 4 points = 12 floats = 3 float4 (fully coalesced)
    float4 a = pts4[3 * t + 0];
    float4 b = pts4[3 * t + 1];
    float4 c = pts4[3 * t + 2];

    float px[4] = {a.x, a.w, b.z, c.y};
    float py[4] = {a.y, b.x, b.w, c.z};
    float pz[4] = {a.z, b.y, c.x, c.w};

    float r[4];
#pragma unroll
    for (int i = 0; i < 4; i++) {
        float x = px[i], y = py[i], z = pz[i];

        int bx = (int)floorf(x);
        int by = (int)floorf(y);
        int bz = (int)floorf(z);

        bool in_dom = (bx >= 0) & (bx < LDIM) &
                      (by >= 0) & (by < LDIM) &
                      (bz >= 0) & (bz < LDIM);

        int cx = min(max(bx, 0), LDIM - 1);
        int cy = min(max(by, 0), LDIM - 1);
        int cz = min(max(bz, 0), LDIM - 1);

        int bidx = __ldg(&lut[cx * (LDIM * LDIM) + cy * LDIM + cz]);
        bool valid = in_dom && (bidx >= 0);

        // Match reference float sequence exactly:
        //   block_x = 2*(p - bcs) - 1
        //   vox = clip(floor((block_x*0.5 + 0.5) * RES), 0, RES-1)
        float bxf = 2.0f * (x - (float)cx) - 1.0f;
        float byf = 2.0f * (y - (float)cy) - 1.0f;
        float bzf = 2.0f * (z - (float)cz) - 1.0f;

        int vx = min(max((int)floorf((bxf * 0.5f + 0.5f) * (float)RES), 0), RES - 1);
        int vy = min(max((int)floorf((byf * 0.5f + 0.5f) * (float)RES), 0), RES - 1);
        int vz = min(max((int)floorf((bzf * 0.5f + 0.5f) * (float)RES), 0), RES - 1);

        float val = 0.0f;
        if (valid) {
            int idx = bidx * (RES * RES * RES) + vx * (RES * RES) + vy * RES + vz;
            val = __ldg(&occ[idx]);
        }
        r[i] = val;
    }

    float4 o;
    o.x = r[0]; o.y = r[1]; o.z = r[2]; o.w = r[3];
    ((float4*)out4)[t] = o;
}

extern "C" void kernel_launch(void* const* d_in, const int* in_sizes, int n_in,
                              void* d_out, int out_size)
{
    const float4* pts4 = (const float4*)d_in[0];
    const float*  occ  = (const float*)d_in[1];
    const int*    lut  = (const int*)d_in[2];
    float*        out  = (float*)d_out;

    int n_pts = in_sizes[0] / 3;       // 4,194,304
    int n4    = n_pts / 4;             // 1,048,576 (N_PTS divisible by 4)

    int threads = 256;
    int blocks  = (n4 + threads - 1) / threads;
    occ_forest_kernel<<<blocks, threads>>>(pts4, occ, lut, out, n4);
}